// round 16
// baseline (speedup 1.0000x reference)
#include <cuda_runtime.h>
#include <cuda_fp16.h>
#include <math.h>
#include <stdint.h>

// ---------------- problem constants ----------------
#define N_INST 64
#define N_PTS  8192
#define HID    256
#define NLAY   5
#define LATENT 64

// ---------------- device scratch (static, allocation-free) ----------------
__device__ __align__(1024) __half g_actAH[(size_t)N_INST * N_PTS * HID];
__device__ __align__(1024) __half g_actAL[(size_t)N_INST * N_PTS * HID];
__device__ __align__(1024) __half g_actBH[(size_t)N_INST * N_PTS * HID];
__device__ __align__(1024) __half g_actBL[(size_t)N_INST * N_PTS * HID];
__device__ __align__(1024) __half g_Wh[(size_t)3 * N_INST * HID * HID];
__device__ __align__(1024) __half g_Wl[(size_t)3 * N_INST * HID * HID];
__device__ __align__(1024) float  g_W0[(size_t)N_INST * 512];
__device__ __align__(1024) float  g_W4[(size_t)N_INST * 768];
__device__ __align__(1024) float  g_Bc[(size_t)NLAY * N_INST * HID];
__device__ float g_tv[(size_t)N_INST * NLAY * 256];
__device__ int   g_ti[(size_t)N_INST * NLAY * 256];

struct GatePtrs {
    const float* gw[5];
    const float* gb[5];
};
struct CombArgs {
    const float* w[5];
    const float* b[5];
};

// ---------------- helpers ----------------
__device__ __forceinline__ uint32_t smem_to_u32(const void* smem_ptr) {
    uint32_t addr;
    asm("{ .reg .u64 tmp; cvta.to.shared.u64 tmp, %1; cvt.u32.u64 %0, tmp; }"
        : "=r"(addr) : "l"(smem_ptr));
    return addr;
}
__device__ __forceinline__ void cp_async16(uint32_t dst, const void* src) {
    asm volatile("cp.async.cg.shared.global [%0], [%1], 16;"
                 :: "r"(dst), "l"(src) : "memory");
}
__device__ __forceinline__ void cp_commit() {
    asm volatile("cp.async.commit_group;" ::: "memory");
}
template <int N>
__device__ __forceinline__ void cp_wait() {
    asm volatile("cp.async.wait_group %0;" :: "n"(N) : "memory");
}
__device__ __forceinline__ void ldm4(uint32_t* r, uint32_t addr) {
    asm volatile("ldmatrix.sync.aligned.m8n8.x4.shared.b16 {%0,%1,%2,%3}, [%4];"
                 : "=r"(r[0]), "=r"(r[1]), "=r"(r[2]), "=r"(r[3]) : "r"(addr));
}
__device__ __forceinline__ void mma_f16(float* d, const uint32_t* a, const uint32_t* b) {
    asm volatile(
        "mma.sync.aligned.m16n8k16.row.col.f32.f16.f16.f32 "
        "{%0,%1,%2,%3}, {%4,%5,%6,%7}, {%8,%9}, {%0,%1,%2,%3};\n"
        : "+f"(d[0]), "+f"(d[1]), "+f"(d[2]), "+f"(d[3])
        : "r"(a[0]), "r"(a[1]), "r"(a[2]), "r"(a[3]), "r"(b[0]), "r"(b[1]));
}

// swizzled byte offset inside a (rows x 64B) tile array
__device__ __forceinline__ uint32_t swz(int row, int c16) {
    return (uint32_t)(row * 64 + ((c16 ^ ((row >> 1) & 3)) << 4));
}

// ---------------- fast sin(30*x) ----------------
__device__ __forceinline__ float sin30f(float x) {
    const float INV_2PI_30 = 4.774648292756860f;
    float t = x * INV_2PI_30;
    float n = __fadd_rn(t, 12582912.0f);
    n = __fadd_rn(n, -12582912.0f);
    float r = t - n;
    float u = r * r;
    float p = 3.8199525797f;
    p = fmaf(p, u, -15.0946425768f);
    p = fmaf(p, u,  42.0586939449f);
    p = fmaf(p, u, -76.7058597531f);
    p = fmaf(p, u,  81.6052492761f);
    p = fmaf(p, u, -41.3417022404f);
    p = fmaf(p, u,   6.2831853072f);
    return r * p;
}

__device__ __forceinline__ void fsplit(float v, __half& h, __half& l) {
    h = __float2half_rn(v);
    l = __float2half_rn(v - __half2float(h));
}

// ---------------- gate + radix-select top-k ----------------
__global__ void gate_kernel(const float* __restrict__ latents, GatePtrs gp) {
    const int l = blockIdx.x;
    const int n = blockIdx.y;
    const int tid = threadIdx.x;

    const int Es[5] = {8, 16, 64, 256, 1024};
    const int Ks[5] = {4, 4, 32, 32, 256};
    const int E = Es[l];
    const int K = Ks[l];

    __shared__ float lat[LATENT];
    __shared__ float gate[1024];
    __shared__ uint32_t keys[1024];
    __shared__ uint8_t act[1024];
    __shared__ int hist[256];
    __shared__ int s_digit, s_rem, s_cnt;

    if (tid < LATENT) lat[tid] = latents[((size_t)n * NLAY + l) * LATENT + tid];
    __syncthreads();

    const float* gw = gp.gw[l];
    const float* gb = gp.gb[l];
    for (int e = tid; e < E; e += 256) {
        const float* row = gw + (size_t)e * LATENT;
        float s = gb[e];
        #pragma unroll 8
        for (int j = 0; j < LATENT; j++) s = fmaf(lat[j], row[j], s);
        gate[e] = s;
        keys[e] = __float_as_uint(fabsf(s));
        act[e] = 1;
    }
    __syncthreads();

    int remaining = K;
    uint32_t T = 0;
    #pragma unroll
    for (int b = 3; b >= 0; b--) {
        hist[tid] = 0;
        __syncthreads();
        for (int e = tid; e < E; e += 256)
            if (act[e]) atomicAdd(&hist[(keys[e] >> (8 * b)) & 255], 1);
        __syncthreads();
        if (tid == 0) {
            int cum = 0, d = 255;
            for (; d > 0; d--) {
                if (cum + hist[d] >= remaining) break;
                cum += hist[d];
            }
            s_digit = d;
            s_rem = remaining - cum;
        }
        __syncthreads();
        int d = s_digit;
        remaining = s_rem;
        for (int e = tid; e < E; e += 256)
            if (act[e] && (int)((keys[e] >> (8 * b)) & 255) != d) act[e] = 0;
        T |= ((uint32_t)d) << (8 * b);
        __syncthreads();
    }

    if (tid == 0) s_cnt = 0;
    __syncthreads();
    const size_t base = ((size_t)n * NLAY + l) * 256;
    for (int e = tid; e < E; e += 256) {
        if (keys[e] > T) {
            int p = atomicAdd(&s_cnt, 1);
            g_ti[base + p] = e;
            g_tv[base + p] = gate[e];
        }
    }
    __syncthreads();
    if (tid == 0) {
        int p = s_cnt;
        for (int e = 0; e < E && p < K; e++) {
            if (keys[e] == T) {
                g_ti[base + p] = e;
                g_tv[base + p] = gate[e];
                p++;
            }
        }
    }
}

// ---------------- combine ALL layers in one launch ----------------
// grid: (N_INST, 16, NLAY) — instance fastest for L2 reuse across instances.
__global__ void combine_all(CombArgs ca) {
    const int n = blockIdx.x;
    const int mt = blockIdx.y;
    const int l = blockIdx.z;
    const int tid = threadIdx.x;

    const int Ks[5]   = {4, 4, 32, 32, 256};
    const int din[5]  = {2, 256, 256, 256, 256};
    const int dout[5] = {256, 256, 256, 256, 3};
    const int K = Ks[l];
    const int dinn = din[l];
    const int dou  = dout[l];
    const int M = dou * dinn;
    const int M4 = M >> 2;

    if (mt * 1024 >= M4 && mt != 0) return;

    __shared__ float sv[256];
    __shared__ int   sw[256];
    __shared__ int   sb[256];
    if (tid < K) {
        sv[tid] = g_tv[((size_t)n * NLAY + l) * 256 + tid];
        int e   = g_ti[((size_t)n * NLAY + l) * 256 + tid];
        sw[tid] = e * M;
        sb[tid] = e * dou;
    }
    __syncthreads();

    const float* wbank = ca.w[l];
    const bool do_split = (l >= 1 && l <= 3);
    float* wout32 = (l == 0) ? (g_W0 + (size_t)n * 512)
                  : (l == 4) ? (g_W4 + (size_t)n * 768) : nullptr;
    const size_t splitbase = do_split ? ((size_t)(l - 1) * N_INST + n) * (HID * HID) : 0;

    int base4 = mt * 1024 + tid;
    #pragma unroll
    for (int it = 0; it < 4; it++) {
        int m4 = base4 + it * 256;
        if (m4 < M4) {
            float4 acc = make_float4(0.f, 0.f, 0.f, 0.f);
            for (int j = 0; j < K; j++) {
                float v = sv[j];
                float4 w = *(const float4*)(wbank + (size_t)sw[j] + m4 * 4);
                acc.x = fmaf(v, w.x, acc.x);
                acc.y = fmaf(v, w.y, acc.y);
                acc.z = fmaf(v, w.z, acc.z);
                acc.w = fmaf(v, w.w, acc.w);
            }
            if (do_split) {
                __half hx, lx, hy, ly, hz, lz, hw, lw;
                fsplit(acc.x, hx, lx); fsplit(acc.y, hy, ly);
                fsplit(acc.z, hz, lz); fsplit(acc.w, hw, lw);
                __half2* ph = (__half2*)(g_Wh + splitbase + m4 * 4);
                __half2* pl = (__half2*)(g_Wl + splitbase + m4 * 4);
                ph[0] = __halves2half2(hx, hy); ph[1] = __halves2half2(hz, hw);
                pl[0] = __halves2half2(lx, ly); pl[1] = __halves2half2(lz, lw);
            } else {
                *(float4*)(wout32 + m4 * 4) = acc;
            }
        }
    }
    if (mt == 0) {
        const float* bbank = ca.b[l];
        float* bout = g_Bc + ((size_t)l * N_INST + n) * HID;
        for (int m = tid; m < dou; m += 256) {
            float s = 0.0f;
            for (int j = 0; j < K; j++) s = fmaf(sv[j], bbank[(size_t)sb[j] + m], s);
            bout[m] = s;
        }
    }
}

// ---------------- layer 0: d_in=2 -> 256, sin, writes split halves ----------------
__global__ void layer0_kernel(const float* __restrict__ coords) {
    const int n  = blockIdx.y;
    const int p0 = blockIdx.x * 64;
    const int o  = threadIdx.x;
    __shared__ float w0[HID], w1[HID], bb[HID];
    w0[o] = g_W0[(size_t)n * 512 + o * 2 + 0];
    w1[o] = g_W0[(size_t)n * 512 + o * 2 + 1];
    bb[o] = g_Bc[((size_t)0 * N_INST + n) * HID + o];
    __syncthreads();
    const float* cn = coords + ((size_t)n * N_PTS) * 2;
    __half* YH = g_actAH + ((size_t)n * N_PTS) * HID;
    __half* YL = g_actAL + ((size_t)n * N_PTS) * HID;
    #pragma unroll 4
    for (int pp = 0; pp < 64; pp++) {
        int p = p0 + pp;
        float x0 = cn[(size_t)p * 2 + 0];
        float x1 = cn[(size_t)p * 2 + 1];
        float v = fmaf(x0, w0[o], fmaf(x1, w1[o], bb[o]));
        float s = sin30f(v);
        __half h, l;
        fsplit(s, h, l);
        YH[(size_t)p * HID + o] = h;
        YL[(size_t)p * HID + o] = l;
    }
}

// ---------------- hidden layers 1-3: pre-split fp16 MMA GEMM ----------------
// CTA 64(M) x 128(N); 4 warps (1x4), warp tile 64x32; K=256 in 8 chunks of 32;
// 2-stage cp.async ring; 4 independent CTAs/SM (unaligned syncs overlap).
#define ST_XH   0
#define ST_XL   4096
#define ST_WH   8192
#define ST_WL   16384
#define STAGE_B 24576
#define GEMM_SMEM_BYTES (512 + 2 * STAGE_B)   // 49,664

// lastL: epilogue writes single fp16 (no split) — layer4 consumes H only.
__global__ void __launch_bounds__(128, 4) gemm_mma(int srcA, int hl, int l, int lastL) {
    extern __shared__ float sm[];
    float* bias = sm;                              // 128 floats
    const uint32_t bufs_u = smem_to_u32(sm + 128);

    const int tid  = threadIdx.x;
    const int lane = tid & 31;
    const int wid  = tid >> 5;     // 0..3 = warpN
    const int g = lane >> 2;
    const int t = lane & 3;

    const __half* XH = srcA ? g_actAH : g_actBH;
    const __half* XL = srcA ? g_actAL : g_actBL;
    __half* YH = srcA ? g_actBH : g_actAH;
    __half* YL = srcA ? g_actBL : g_actAL;

    const int n  = blockIdx.z;
    const int p0 = blockIdx.x * 64;
    const int o0 = blockIdx.y * 128;
    const __half* XnH = XH + (size_t)n * N_PTS * HID;
    const __half* XnL = XL + (size_t)n * N_PTS * HID;
    const size_t wbase = ((size_t)hl * N_INST + n) * (HID * HID) + (size_t)o0 * HID;
    const __half* WhN = g_Wh + wbase;
    const __half* WlN = g_Wl + wbase;
    __half* YnH = YH + (size_t)n * N_PTS * HID;
    __half* YnL = YL + (size_t)n * N_PTS * HID;

    bias[tid] = g_Bc[((size_t)l * N_INST + n) * HID + o0 + tid];

    auto issue_chunk = [&](int kc, int st) {
        const uint32_t sb = bufs_u + (uint32_t)st * STAGE_B;
        const int k0 = kc * 32;                    // halves
        #pragma unroll
        for (int i = 0; i < 4; i++) {              // X: H/L x 64 rows x 4 c16 = 512
            const int f = i * 128 + tid;
            const int arr = f >> 8;
            const int row = (f >> 2) & 63;
            const int c16 = f & 3;
            const __half* src = (arr ? XnL : XnH) + (size_t)(p0 + row) * HID + k0 + c16 * 8;
            cp_async16(sb + (arr ? ST_XL : ST_XH) + swz(row, c16), src);
        }
        #pragma unroll
        for (int i = 0; i < 8; i++) {              // W: H/L x 128 rows x 4 c16 = 1024
            const int f = i * 128 + tid;
            const int arr = f >> 9;
            const int row = (f >> 2) & 127;
            const int c16 = f & 3;
            const __half* src = (arr ? WlN : WhN) + (size_t)row * HID + k0 + c16 * 8;
            cp_async16(sb + (arr ? ST_WL : ST_WH) + swz(row, c16), src);
        }
        cp_commit();
    };

    float acc[4][4][4];
    #pragma unroll
    for (int i = 0; i < 4; i++)
        #pragma unroll
        for (int j = 0; j < 4; j++)
            #pragma unroll
            for (int q = 0; q < 4; q++) acc[i][j][q] = 0.0f;

    issue_chunk(0, 0);
    issue_chunk(1, 1);

    #pragma unroll 1
    for (int kc = 0; kc < 8; kc++) {
        if (kc < 7) cp_wait<1>(); else cp_wait<0>();
        __syncthreads();

        const uint32_t sb = bufs_u + (uint32_t)(kc & 1) * STAGE_B;

        #pragma unroll
        for (int step = 0; step < 2; step++) {
            uint32_t ah[4][4], al[4][4];
            #pragma unroll
            for (int i = 0; i < 4; i++) {
                const int ar = i * 16 + (lane & 15);
                const int ac = (lane >> 4) + step * 2;
                ldm4(ah[i], sb + ST_XH + swz(ar, ac));
                ldm4(al[i], sb + ST_XL + swz(ar, ac));
            }
            #pragma unroll
            for (int jp = 0; jp < 2; jp++) {
                const int br = wid * 32 + jp * 16 + (lane & 7) + ((lane >> 4) << 3);
                const int bc = ((lane >> 3) & 1) + step * 2;
                uint32_t bh4[4], bl4[4];
                ldm4(bh4, sb + ST_WH + swz(br, bc));
                ldm4(bl4, sb + ST_WL + swz(br, bc));
                #pragma unroll
                for (int i = 0; i < 4; i++) {
                    mma_f16(acc[i][2 * jp + 0], ah[i], bh4 + 0);
                    mma_f16(acc[i][2 * jp + 1], ah[i], bh4 + 2);
                }
                #pragma unroll
                for (int i = 0; i < 4; i++) {
                    mma_f16(acc[i][2 * jp + 0], ah[i], bl4 + 0);
                    mma_f16(acc[i][2 * jp + 1], ah[i], bl4 + 2);
                }
                #pragma unroll
                for (int i = 0; i < 4; i++) {
                    mma_f16(acc[i][2 * jp + 0], al[i], bh4 + 0);
                    mma_f16(acc[i][2 * jp + 1], al[i], bh4 + 2);
                }
            }
        }

        __syncthreads();                 // stage (kc&1) fully consumed
        if (kc + 2 < 8) issue_chunk(kc + 2, kc & 1);
    }

    // epilogue: bias + sin(30x)
    #pragma unroll
    for (int i = 0; i < 4; i++) {
        const int rg = p0 + i * 16 + g;
        #pragma unroll
        for (int j = 0; j < 4; j++) {
            const int cl = wid * 32 + j * 8 + t * 2;
            const float b0 = bias[cl], b1 = bias[cl + 1];
            float s00 = sin30f(acc[i][j][0] + b0);
            float s01 = sin30f(acc[i][j][1] + b1);
            float s10 = sin30f(acc[i][j][2] + b0);
            float s11 = sin30f(acc[i][j][3] + b1);
            if (lastL) {
                *(__half2*)(YnH + (size_t)rg * HID + o0 + cl) =
                    __floats2half2_rn(s00, s01);
                *(__half2*)(YnH + (size_t)(rg + 8) * HID + o0 + cl) =
                    __floats2half2_rn(s10, s11);
            } else {
                __half h00, l00, h01, l01, h10, l10, h11, l11;
                fsplit(s00, h00, l00); fsplit(s01, h01, l01);
                fsplit(s10, h10, l10); fsplit(s11, h11, l11);
                *(__half2*)(YnH + (size_t)rg * HID + o0 + cl)       = __halves2half2(h00, h01);
                *(__half2*)(YnL + (size_t)rg * HID + o0 + cl)       = __halves2half2(l00, l01);
                *(__half2*)(YnH + (size_t)(rg + 8) * HID + o0 + cl) = __halves2half2(h10, h11);
                *(__half2*)(YnL + (size_t)(rg + 8) * HID + o0 + cl) = __halves2half2(l10, l11);
            }
        }
    }
}

// ---------------- layer 4: 256 -> 3, reads H only, W in registers ----------------
__global__ void layer4_kernel(float* __restrict__ out) {
    const int n = blockIdx.y;
    const int warp = threadIdx.x >> 5;
    const int lane = threadIdx.x & 31;
    const int pbase = (blockIdx.x * 8 + warp) * 8;

    float w[3][8];
    #pragma unroll
    for (int o = 0; o < 3; o++) {
        const float* wp = g_W4 + (size_t)n * 768 + o * HID + lane * 8;
        #pragma unroll
        for (int q = 0; q < 8; q++) w[o][q] = wp[q];
    }
    const float* bb = g_Bc + ((size_t)4 * N_INST + n) * HID;
    float b0 = bb[0], b1 = bb[1], b2 = bb[2];

    #pragma unroll 1
    for (int pp = 0; pp < 8; pp++) {
        const int p = pbase + pp;
        const size_t base = ((size_t)n * N_PTS + p) * HID + lane * 8;
        const __half2* xh = (const __half2*)(g_actBH + base);
        float x[8];
        #pragma unroll
        for (int q = 0; q < 4; q++) {
            float2 h = __half22float2(xh[q]);
            x[2 * q + 0] = h.x;
            x[2 * q + 1] = h.y;
        }
        float s[3];
        #pragma unroll
        for (int o = 0; o < 3; o++) {
            float t = 0.0f;
            #pragma unroll
            for (int q = 0; q < 8; q++) t = fmaf(x[q], w[o][q], t);
            s[o] = t;
        }
        #pragma unroll
        for (int off = 16; off > 0; off >>= 1) {
            #pragma unroll
            for (int o = 0; o < 3; o++) s[o] += __shfl_xor_sync(0xFFFFFFFFu, s[o], off);
        }
        if (lane == 0) {
            float* op = out + ((size_t)n * N_PTS + p) * 3;
            op[0] = s[0] + b0;
            op[1] = s[1] + b1;
            op[2] = s[2] + b2;
        }
    }
}

// ---------------- host launch ----------------
extern "C" void kernel_launch(void* const* d_in, const int* in_sizes, int n_in,
                              void* d_out, int out_size) {
    const float* latents = (const float*)d_in[0];
    const float* coords  = (const float*)d_in[1];
    const float *gw[5], *gb[5], *w[5], *b[5];

    bool interleaved = (in_sizes[3] == 8); // gb0 has 8 elements
    if (interleaved) {
        for (int i = 0; i < 5; i++) {
            gw[i] = (const float*)d_in[2 + 2 * i];
            gb[i] = (const float*)d_in[3 + 2 * i];
            w[i]  = (const float*)d_in[12 + 2 * i];
            b[i]  = (const float*)d_in[13 + 2 * i];
        }
    } else {
        for (int i = 0; i < 5; i++) {
            gw[i] = (const float*)d_in[2 + i];
            gb[i] = (const float*)d_in[7 + i];
            w[i]  = (const float*)d_in[12 + i];
            b[i]  = (const float*)d_in[17 + i];
        }
    }

    GatePtrs gp;
    CombArgs ca;
    for (int i = 0; i < 5; i++) {
        gp.gw[i] = gw[i]; gp.gb[i] = gb[i];
        ca.w[i]  = w[i];  ca.b[i]  = b[i];
    }

    cudaFuncSetAttribute(gemm_mma, cudaFuncAttributeMaxDynamicSharedMemorySize,
                         GEMM_SMEM_BYTES);

    gate_kernel<<<dim3(NLAY, N_INST), 256>>>(latents, gp);
    combine_all<<<dim3(N_INST, 16, NLAY), 256>>>(ca);
    layer0_kernel<<<dim3(N_PTS / 64, N_INST), 256>>>(coords);
    for (int l = 1; l <= 3; l++) {
        int srcA = (l & 1);   // l=1: A->B, l=2: B->A, l=3: A->B
        gemm_mma<<<dim3(N_PTS / 64, HID / 128, N_INST), 128, GEMM_SMEM_BYTES>>>(
            srcA, l - 1, l, l == 3 ? 1 : 0);
    }
    layer4_kernel<<<dim3(N_PTS / 64, N_INST), 256>>>((float*)d_out);
}

// round 17
// speedup vs baseline: 1.0793x; 1.0793x over previous
#include <cuda_runtime.h>
#include <cuda_fp16.h>
#include <math.h>
#include <stdint.h>

// ---------------- problem constants ----------------
#define N_INST 64
#define N_PTS  8192
#define HID    256
#define NLAY   5
#define LATENT 64

// ---------------- device scratch (static, allocation-free) ----------------
__device__ __align__(1024) __half g_actAH[(size_t)N_INST * N_PTS * HID];
__device__ __align__(1024) __half g_actAL[(size_t)N_INST * N_PTS * HID];
__device__ __align__(1024) __half g_actBH[(size_t)N_INST * N_PTS * HID];
__device__ __align__(1024) __half g_actBL[(size_t)N_INST * N_PTS * HID];
__device__ __align__(1024) __half g_Wh[(size_t)3 * N_INST * HID * HID];
__device__ __align__(1024) __half g_Wl[(size_t)3 * N_INST * HID * HID];
__device__ __align__(1024) float  g_W0[(size_t)N_INST * 512];
__device__ __align__(1024) float  g_W4[(size_t)N_INST * 768];
__device__ __align__(1024) float  g_Bc[(size_t)NLAY * N_INST * HID];
__device__ float g_tv[(size_t)N_INST * NLAY * 256];
__device__ int   g_ti[(size_t)N_INST * NLAY * 256];

struct GatePtrs {
    const float* gw[5];
    const float* gb[5];
};
struct CombArgs {
    const float* w[5];
    const float* b[5];
};

// ---------------- helpers ----------------
__device__ __forceinline__ uint32_t smem_to_u32(const void* smem_ptr) {
    uint32_t addr;
    asm("{ .reg .u64 tmp; cvta.to.shared.u64 tmp, %1; cvt.u32.u64 %0, tmp; }"
        : "=r"(addr) : "l"(smem_ptr));
    return addr;
}
__device__ __forceinline__ void cp_async16(uint32_t dst, const void* src) {
    asm volatile("cp.async.cg.shared.global [%0], [%1], 16;"
                 :: "r"(dst), "l"(src) : "memory");
}
__device__ __forceinline__ void cp_commit() {
    asm volatile("cp.async.commit_group;" ::: "memory");
}
template <int N>
__device__ __forceinline__ void cp_wait() {
    asm volatile("cp.async.wait_group %0;" :: "n"(N) : "memory");
}
__device__ __forceinline__ void ldm4(uint32_t* r, uint32_t addr) {
    asm volatile("ldmatrix.sync.aligned.m8n8.x4.shared.b16 {%0,%1,%2,%3}, [%4];"
                 : "=r"(r[0]), "=r"(r[1]), "=r"(r[2]), "=r"(r[3]) : "r"(addr));
}
__device__ __forceinline__ void mma_f16(float* d, const uint32_t* a, const uint32_t* b) {
    asm volatile(
        "mma.sync.aligned.m16n8k16.row.col.f32.f16.f16.f32 "
        "{%0,%1,%2,%3}, {%4,%5,%6,%7}, {%8,%9}, {%0,%1,%2,%3};\n"
        : "+f"(d[0]), "+f"(d[1]), "+f"(d[2]), "+f"(d[3])
        : "r"(a[0]), "r"(a[1]), "r"(a[2]), "r"(a[3]), "r"(b[0]), "r"(b[1]));
}

// swizzled byte offset inside a (rows x 64B) tile array
__device__ __forceinline__ uint32_t swz(int row, int c16) {
    return (uint32_t)(row * 64 + ((c16 ^ ((row >> 1) & 3)) << 4));
}

// ---------------- fast sin(30*x) ----------------
__device__ __forceinline__ float sin30f(float x) {
    const float INV_2PI_30 = 4.774648292756860f;
    float t = x * INV_2PI_30;
    float n = __fadd_rn(t, 12582912.0f);
    n = __fadd_rn(n, -12582912.0f);
    float r = t - n;
    float u = r * r;
    float p = 3.8199525797f;
    p = fmaf(p, u, -15.0946425768f);
    p = fmaf(p, u,  42.0586939449f);
    p = fmaf(p, u, -76.7058597531f);
    p = fmaf(p, u,  81.6052492761f);
    p = fmaf(p, u, -41.3417022404f);
    p = fmaf(p, u,   6.2831853072f);
    return r * p;
}

__device__ __forceinline__ void fsplit(float v, __half& h, __half& l) {
    h = __float2half_rn(v);
    l = __float2half_rn(v - __half2float(h));
}

// ---------------- out init: out[n][p][o] = bias4[n][o] ----------------
__global__ void init_out(float* __restrict__ out) {
    const int idx = blockIdx.x * 256 + threadIdx.x;
    const int total = N_INST * N_PTS * 3;
    if (idx < total) {
        int o = idx % 3;
        int n = idx / (N_PTS * 3);
        out[idx] = g_Bc[((size_t)4 * N_INST + n) * HID + o];
    }
}

// ---------------- gate + radix-select top-k ----------------
__global__ void gate_kernel(const float* __restrict__ latents, GatePtrs gp) {
    const int l = blockIdx.x;
    const int n = blockIdx.y;
    const int tid = threadIdx.x;

    const int Es[5] = {8, 16, 64, 256, 1024};
    const int Ks[5] = {4, 4, 32, 32, 256};
    const int E = Es[l];
    const int K = Ks[l];

    __shared__ float lat[LATENT];
    __shared__ float gate[1024];
    __shared__ uint32_t keys[1024];
    __shared__ uint8_t act[1024];
    __shared__ int hist[256];
    __shared__ int s_digit, s_rem, s_cnt;

    if (tid < LATENT) lat[tid] = latents[((size_t)n * NLAY + l) * LATENT + tid];
    __syncthreads();

    const float* gw = gp.gw[l];
    const float* gb = gp.gb[l];
    for (int e = tid; e < E; e += 256) {
        const float* row = gw + (size_t)e * LATENT;
        float s = gb[e];
        #pragma unroll 8
        for (int j = 0; j < LATENT; j++) s = fmaf(lat[j], row[j], s);
        gate[e] = s;
        keys[e] = __float_as_uint(fabsf(s));
        act[e] = 1;
    }
    __syncthreads();

    int remaining = K;
    uint32_t T = 0;
    #pragma unroll
    for (int b = 3; b >= 0; b--) {
        hist[tid] = 0;
        __syncthreads();
        for (int e = tid; e < E; e += 256)
            if (act[e]) atomicAdd(&hist[(keys[e] >> (8 * b)) & 255], 1);
        __syncthreads();
        if (tid == 0) {
            int cum = 0, d = 255;
            for (; d > 0; d--) {
                if (cum + hist[d] >= remaining) break;
                cum += hist[d];
            }
            s_digit = d;
            s_rem = remaining - cum;
        }
        __syncthreads();
        int d = s_digit;
        remaining = s_rem;
        for (int e = tid; e < E; e += 256)
            if (act[e] && (int)((keys[e] >> (8 * b)) & 255) != d) act[e] = 0;
        T |= ((uint32_t)d) << (8 * b);
        __syncthreads();
    }

    if (tid == 0) s_cnt = 0;
    __syncthreads();
    const size_t base = ((size_t)n * NLAY + l) * 256;
    for (int e = tid; e < E; e += 256) {
        if (keys[e] > T) {
            int p = atomicAdd(&s_cnt, 1);
            g_ti[base + p] = e;
            g_tv[base + p] = gate[e];
        }
    }
    __syncthreads();
    if (tid == 0) {
        int p = s_cnt;
        for (int e = 0; e < E && p < K; e++) {
            if (keys[e] == T) {
                g_ti[base + p] = e;
                g_tv[base + p] = gate[e];
                p++;
            }
        }
    }
}

// ---------------- combine ALL layers in one launch ----------------
__global__ void combine_all(CombArgs ca) {
    const int n = blockIdx.x;
    const int mt = blockIdx.y;
    const int l = blockIdx.z;
    const int tid = threadIdx.x;

    const int Ks[5]   = {4, 4, 32, 32, 256};
    const int din[5]  = {2, 256, 256, 256, 256};
    const int dout[5] = {256, 256, 256, 256, 3};
    const int K = Ks[l];
    const int dinn = din[l];
    const int dou  = dout[l];
    const int M = dou * dinn;
    const int M4 = M >> 2;

    if (mt * 1024 >= M4 && mt != 0) return;

    __shared__ float sv[256];
    __shared__ int   sw[256];
    __shared__ int   sb[256];
    if (tid < K) {
        sv[tid] = g_tv[((size_t)n * NLAY + l) * 256 + tid];
        int e   = g_ti[((size_t)n * NLAY + l) * 256 + tid];
        sw[tid] = e * M;
        sb[tid] = e * dou;
    }
    __syncthreads();

    const float* wbank = ca.w[l];
    const bool do_split = (l >= 1 && l <= 3);
    float* wout32 = (l == 0) ? (g_W0 + (size_t)n * 512)
                  : (l == 4) ? (g_W4 + (size_t)n * 768) : nullptr;
    const size_t splitbase = do_split ? ((size_t)(l - 1) * N_INST + n) * (HID * HID) : 0;

    int base4 = mt * 1024 + tid;
    #pragma unroll
    for (int it = 0; it < 4; it++) {
        int m4 = base4 + it * 256;
        if (m4 < M4) {
            float4 acc = make_float4(0.f, 0.f, 0.f, 0.f);
            for (int j = 0; j < K; j++) {
                float v = sv[j];
                float4 w = *(const float4*)(wbank + (size_t)sw[j] + m4 * 4);
                acc.x = fmaf(v, w.x, acc.x);
                acc.y = fmaf(v, w.y, acc.y);
                acc.z = fmaf(v, w.z, acc.z);
                acc.w = fmaf(v, w.w, acc.w);
            }
            if (do_split) {
                __half hx, lx, hy, ly, hz, lz, hw, lw;
                fsplit(acc.x, hx, lx); fsplit(acc.y, hy, ly);
                fsplit(acc.z, hz, lz); fsplit(acc.w, hw, lw);
                __half2* ph = (__half2*)(g_Wh + splitbase + m4 * 4);
                __half2* pl = (__half2*)(g_Wl + splitbase + m4 * 4);
                ph[0] = __halves2half2(hx, hy); ph[1] = __halves2half2(hz, hw);
                pl[0] = __halves2half2(lx, ly); pl[1] = __halves2half2(lz, lw);
            } else {
                *(float4*)(wout32 + m4 * 4) = acc;
            }
        }
    }
    if (mt == 0) {
        const float* bbank = ca.b[l];
        float* bout = g_Bc + ((size_t)l * N_INST + n) * HID;
        for (int m = tid; m < dou; m += 256) {
            float s = 0.0f;
            for (int j = 0; j < K; j++) s = fmaf(sv[j], bbank[(size_t)sb[j] + m], s);
            bout[m] = s;
        }
    }
}

// ---------------- layer 0: d_in=2 -> 256, sin, vectorized split stores ----------------
// 8 warps/CTA; each warp does 8 points; lane owns 8 contiguous channels.
__global__ void layer0_kernel(const float* __restrict__ coords) {
    const int n  = blockIdx.y;
    const int p0 = blockIdx.x * 64;
    const int warp = threadIdx.x >> 5;
    const int lane = threadIdx.x & 31;

    float w0[8], w1[8], bb[8];
    #pragma unroll
    for (int q = 0; q < 8; q++) {
        int o = lane * 8 + q;
        w0[q] = g_W0[(size_t)n * 512 + o * 2 + 0];
        w1[q] = g_W0[(size_t)n * 512 + o * 2 + 1];
        bb[q] = g_Bc[((size_t)0 * N_INST + n) * HID + o];
    }
    const float* cn = coords + ((size_t)n * N_PTS) * 2;
    __half* YH = g_actAH + ((size_t)n * N_PTS) * HID;
    __half* YL = g_actAL + ((size_t)n * N_PTS) * HID;

    #pragma unroll 1
    for (int pp = 0; pp < 8; pp++) {
        const int p = p0 + warp * 8 + pp;
        float x0 = cn[(size_t)p * 2 + 0];
        float x1 = cn[(size_t)p * 2 + 1];
        __half2 H[4], L[4];
        #pragma unroll
        for (int q2 = 0; q2 < 4; q2++) {
            float s0 = sin30f(fmaf(x0, w0[2 * q2 + 0], fmaf(x1, w1[2 * q2 + 0], bb[2 * q2 + 0])));
            float s1 = sin30f(fmaf(x0, w0[2 * q2 + 1], fmaf(x1, w1[2 * q2 + 1], bb[2 * q2 + 1])));
            __half h0, l0, h1, l1;
            fsplit(s0, h0, l0); fsplit(s1, h1, l1);
            H[q2] = __halves2half2(h0, h1);
            L[q2] = __halves2half2(l0, l1);
        }
        *(float4*)(YH + (size_t)p * HID + lane * 8) = *(float4*)H;
        *(float4*)(YL + (size_t)p * HID + lane * 8) = *(float4*)L;
    }
}

// ---------------- hidden layers: pre-split fp16 MMA GEMM (R15 shape) ----------------
// CTA 128(M) x 128(N); warp tile 64x32; K=256 in 8 chunks of 32 halves;
// 3-stage cp.async ring; 2 CTAs/SM.
// LASTL=1: layer-4 fused into the epilogue (dot with W4, smem+shfl reduce,
//          atomicAdd partials into out). out pre-initialized with bias4.
#define ST_XH   0
#define ST_XL   8192
#define ST_WH   16384
#define ST_WL   24576
#define STAGE_B 32768
#define NSTAGE  3
// header: bias[128] floats + W4sh[768] floats = 3584 B
#define GEMM_SMEM_BYTES (3584 + NSTAGE * STAGE_B)   // 101,888

template <int LASTL>
__global__ void __launch_bounds__(256, 2) gemm_mma(int srcA, int hl, int l,
                                                   float* __restrict__ out) {
    extern __shared__ float sm[];
    float* bias = sm;                              // 128 floats
    float* W4sh = sm + 128;                        // 768 floats (LASTL only)
    const uint32_t bufs_u = smem_to_u32(sm + 896);
    float* red = sm + 896;                         // aliases stage 0 (post-mainloop)

    const int tid  = threadIdx.x;
    const int lane = tid & 31;
    const int wid  = tid >> 5;
    const int g = lane >> 2;
    const int t = lane & 3;
    const int warpM = wid & 1;     // 64 rows each
    const int warpN = wid >> 1;    // 32 cols each

    const __half* XH = srcA ? g_actAH : g_actBH;
    const __half* XL = srcA ? g_actAL : g_actBL;
    __half* YH = srcA ? g_actBH : g_actAH;
    __half* YL = srcA ? g_actBL : g_actAL;

    const int n  = blockIdx.z;
    const int p0 = blockIdx.x * 128;
    const int o0 = blockIdx.y * 128;
    const __half* XnH = XH + (size_t)n * N_PTS * HID;
    const __half* XnL = XL + (size_t)n * N_PTS * HID;
    const size_t wbase = ((size_t)hl * N_INST + n) * (HID * HID) + (size_t)o0 * HID;
    const __half* WhN = g_Wh + wbase;
    const __half* WlN = g_Wl + wbase;
    __half* YnH = YH + (size_t)n * N_PTS * HID;
    __half* YnL = YL + (size_t)n * N_PTS * HID;

    if (tid < 128) bias[tid] = g_Bc[((size_t)l * N_INST + n) * HID + o0 + tid];
    if (LASTL) {
        #pragma unroll
        for (int q = 0; q < 3; q++)
            W4sh[q * 256 + tid] = g_W4[(size_t)n * 768 + q * 256 + tid];
    }

    auto issue_chunk = [&](int kc, int st) {
        const uint32_t sb = bufs_u + (uint32_t)st * STAGE_B;
        const int k0 = kc * 32;                    // halves
        #pragma unroll
        for (int i = 0; i < 4; i++) {              // X: H/L x 128 rows x 4 c16
            const int f = i * 256 + tid;
            const int arr = f >> 9;
            const int row = (f >> 2) & 127;
            const int c16 = f & 3;
            const __half* src = (arr ? XnL : XnH) + (size_t)(p0 + row) * HID + k0 + c16 * 8;
            cp_async16(sb + (arr ? ST_XL : ST_XH) + swz(row, c16), src);
        }
        #pragma unroll
        for (int i = 0; i < 4; i++) {              // W: H/L x 128 rows x 4 c16
            const int f = i * 256 + tid;
            const int arr = f >> 9;
            const int row = (f >> 2) & 127;
            const int c16 = f & 3;
            const __half* src = (arr ? WlN : WhN) + (size_t)row * HID + k0 + c16 * 8;
            cp_async16(sb + (arr ? ST_WL : ST_WH) + swz(row, c16), src);
        }
        cp_commit();
    };

    float acc[4][4][4];
    #pragma unroll
    for (int i = 0; i < 4; i++)
        #pragma unroll
        for (int j = 0; j < 4; j++)
            #pragma unroll
            for (int q = 0; q < 4; q++) acc[i][j][q] = 0.0f;

    issue_chunk(0, 0);
    issue_chunk(1, 1);

    #pragma unroll 1
    for (int kc = 0; kc < 8; kc++) {
        if (kc < 7) cp_wait<1>(); else cp_wait<0>();
        __syncthreads();
        if (kc + 2 < 8) issue_chunk(kc + 2, (kc + 2) % 3);

        const uint32_t sb = bufs_u + (uint32_t)(kc % 3) * STAGE_B;

        #pragma unroll
        for (int step = 0; step < 2; step++) {
            uint32_t ah[4][4], al[4][4];
            #pragma unroll
            for (int i = 0; i < 4; i++) {
                const int ar = warpM * 64 + i * 16 + (lane & 15);
                const int ac = (lane >> 4) + step * 2;
                ldm4(ah[i], sb + ST_XH + swz(ar, ac));
                ldm4(al[i], sb + ST_XL + swz(ar, ac));
            }
            #pragma unroll
            for (int jp = 0; jp < 2; jp++) {
                const int br = warpN * 32 + jp * 16 + (lane & 7) + ((lane >> 4) << 3);
                const int bc = ((lane >> 3) & 1) + step * 2;
                uint32_t bh4[4], bl4[4];
                ldm4(bh4, sb + ST_WH + swz(br, bc));
                ldm4(bl4, sb + ST_WL + swz(br, bc));
                #pragma unroll
                for (int i = 0; i < 4; i++) {
                    mma_f16(acc[i][2 * jp + 0], ah[i], bh4 + 0);
                    mma_f16(acc[i][2 * jp + 1], ah[i], bh4 + 2);
                }
                #pragma unroll
                for (int i = 0; i < 4; i++) {
                    mma_f16(acc[i][2 * jp + 0], ah[i], bl4 + 0);
                    mma_f16(acc[i][2 * jp + 1], ah[i], bl4 + 2);
                }
                #pragma unroll
                for (int i = 0; i < 4; i++) {
                    mma_f16(acc[i][2 * jp + 0], al[i], bh4 + 0);
                    mma_f16(acc[i][2 * jp + 1], al[i], bh4 + 2);
                }
            }
        }
    }

    if (!LASTL) {
        // epilogue: bias + sin(30x), split to halves, half2 stores
        #pragma unroll
        for (int i = 0; i < 4; i++) {
            const int rg = p0 + warpM * 64 + i * 16 + g;
            #pragma unroll
            for (int j = 0; j < 4; j++) {
                const int cl = warpN * 32 + j * 8 + t * 2;
                const float b0 = bias[cl], b1 = bias[cl + 1];
                float s00 = sin30f(acc[i][j][0] + b0);
                float s01 = sin30f(acc[i][j][1] + b1);
                float s10 = sin30f(acc[i][j][2] + b0);
                float s11 = sin30f(acc[i][j][3] + b1);
                __half h00, l00, h01, l01, h10, l10, h11, l11;
                fsplit(s00, h00, l00); fsplit(s01, h01, l01);
                fsplit(s10, h10, l10); fsplit(s11, h11, l11);
                *(__half2*)(YnH + (size_t)rg * HID + o0 + cl)       = __halves2half2(h00, h01);
                *(__half2*)(YnL + (size_t)rg * HID + o0 + cl)       = __halves2half2(l00, l01);
                *(__half2*)(YnH + (size_t)(rg + 8) * HID + o0 + cl) = __halves2half2(h10, h11);
                *(__half2*)(YnL + (size_t)(rg + 8) * HID + o0 + cl) = __halves2half2(l10, l11);
            }
        }
    } else {
        // fused layer 4: per-thread partial dots of sin values against W4
        // (mainloop fully drained: stage ring reusable as reduction scratch)
        #pragma unroll
        for (int i = 0; i < 4; i++) {
            const int rA = warpM * 64 + i * 16 + g;      // local row
            float pa0 = 0.f, pa1 = 0.f, pa2 = 0.f;
            float pb0 = 0.f, pb1 = 0.f, pb2 = 0.f;
            #pragma unroll
            for (int j = 0; j < 4; j++) {
                const int cl = warpN * 32 + j * 8 + t * 2;
                const int c = o0 + cl;
                const float b0 = bias[cl], b1 = bias[cl + 1];
                float s00 = sin30f(acc[i][j][0] + b0);
                float s01 = sin30f(acc[i][j][1] + b1);
                float s10 = sin30f(acc[i][j][2] + b0);
                float s11 = sin30f(acc[i][j][3] + b1);
                const float wa0 = W4sh[c],        wa1 = W4sh[c + 1];
                const float wb0 = W4sh[256 + c],  wb1 = W4sh[256 + c + 1];
                const float wc0 = W4sh[512 + c],  wc1 = W4sh[512 + c + 1];
                pa0 = fmaf(s00, wa0, fmaf(s01, wa1, pa0));
                pa1 = fmaf(s00, wb0, fmaf(s01, wb1, pa1));
                pa2 = fmaf(s00, wc0, fmaf(s01, wc1, pa2));
                pb0 = fmaf(s10, wa0, fmaf(s11, wa1, pb0));
                pb1 = fmaf(s10, wb0, fmaf(s11, wb1, pb1));
                pb2 = fmaf(s10, wc0, fmaf(s11, wc1, pb2));
            }
            // reduce over t (lanes g*4 + t)
            #pragma unroll
            for (int off = 1; off <= 2; off <<= 1) {
                pa0 += __shfl_xor_sync(0xFFFFFFFFu, pa0, off);
                pa1 += __shfl_xor_sync(0xFFFFFFFFu, pa1, off);
                pa2 += __shfl_xor_sync(0xFFFFFFFFu, pa2, off);
                pb0 += __shfl_xor_sync(0xFFFFFFFFu, pb0, off);
                pb1 += __shfl_xor_sync(0xFFFFFFFFu, pb1, off);
                pb2 += __shfl_xor_sync(0xFFFFFFFFu, pb2, off);
            }
            if (t == 0) {
                float* rp = red + ((size_t)rA * 4 + warpN) * 3;
                rp[0] = pa0; rp[1] = pa1; rp[2] = pa2;
                float* rq = red + ((size_t)(rA + 8) * 4 + warpN) * 3;
                rq[0] = pb0; rq[1] = pb1; rq[2] = pb2;
            }
        }
        __syncthreads();
        if (tid < 128) {
            const int row = tid;
            float v0 = 0.f, v1 = 0.f, v2 = 0.f;
            #pragma unroll
            for (int wN = 0; wN < 4; wN++) {
                const float* rp = red + ((size_t)row * 4 + wN) * 3;
                v0 += rp[0]; v1 += rp[1]; v2 += rp[2];
            }
            float* op = out + ((size_t)n * N_PTS + p0 + row) * 3;
            atomicAdd(op + 0, v0);
            atomicAdd(op + 1, v1);
            atomicAdd(op + 2, v2);
        }
    }
}

// ---------------- host launch ----------------
extern "C" void kernel_launch(void* const* d_in, const int* in_sizes, int n_in,
                              void* d_out, int out_size) {
    const float* latents = (const float*)d_in[0];
    const float* coords  = (const float*)d_in[1];
    const float *gw[5], *gb[5], *w[5], *b[5];

    bool interleaved = (in_sizes[3] == 8); // gb0 has 8 elements
    if (interleaved) {
        for (int i = 0; i < 5; i++) {
            gw[i] = (const float*)d_in[2 + 2 * i];
            gb[i] = (const float*)d_in[3 + 2 * i];
            w[i]  = (const float*)d_in[12 + 2 * i];
            b[i]  = (const float*)d_in[13 + 2 * i];
        }
    } else {
        for (int i = 0; i < 5; i++) {
            gw[i] = (const float*)d_in[2 + i];
            gb[i] = (const float*)d_in[7 + i];
            w[i]  = (const float*)d_in[12 + i];
            b[i]  = (const float*)d_in[17 + i];
        }
    }

    GatePtrs gp;
    CombArgs ca;
    for (int i = 0; i < 5; i++) {
        gp.gw[i] = gw[i]; gp.gb[i] = gb[i];
        ca.w[i]  = w[i];  ca.b[i]  = b[i];
    }

    cudaFuncSetAttribute(gemm_mma<0>, cudaFuncAttributeMaxDynamicSharedMemorySize,
                         GEMM_SMEM_BYTES);
    cudaFuncSetAttribute(gemm_mma<1>, cudaFuncAttributeMaxDynamicSharedMemorySize,
                         GEMM_SMEM_BYTES);

    float* out = (float*)d_out;

    gate_kernel<<<dim3(NLAY, N_INST), 256>>>(latents, gp);
    combine_all<<<dim3(N_INST, 16, NLAY), 256>>>(ca);
    init_out<<<(N_INST * N_PTS * 3 + 255) / 256, 256>>>(out);
    layer0_kernel<<<dim3(N_PTS / 64, N_INST), 256>>>(coords);
    // l=1: A->B, l=2: B->A, l=3 (fused layer4): reads A, writes out
    gemm_mma<0><<<dim3(N_PTS / 128, HID / 128, N_INST), 256, GEMM_SMEM_BYTES>>>(
        1, 0, 1, out);
    gemm_mma<0><<<dim3(N_PTS / 128, HID / 128, N_INST), 256, GEMM_SMEM_BYTES>>>(
        0, 1, 2, out);
    gemm_mma<1><<<dim3(N_PTS / 128, HID / 128, N_INST), 256, GEMM_SMEM_BYTES>>>(
        1, 2, 3, out);
}